// round 8
// baseline (speedup 1.0000x reference)
#include <cuda_runtime.h>
#include <cstdint>

// Problem constants (fixed shapes per reference setup_inputs)
#define BV 4
#define CV 1024
#define HV 64
#define WV 64
#define SV (HV*WV)          // 4096 spatial positions
#define AHV 7
#define AWV 7
#define NBINS (AHV*AWV)     // 49
#define CGRP 128            // channels per block (one permuted group)
#define SPATIAL_SCALE 0.0625f

// Scratch: features as [B, H, W, C'] where C' is permuted within each
// 128-channel group: position p holds channel (p%4)*32 + p/4, i.e. the
// float4 at lane L contains channels {L, L+32, L+64, L+96}.
// 64 MiB static device allocation (allowed scratch).
__device__ float g_feat_t[(size_t)BV * HV * WV * CV];

__device__ __forceinline__ uint32_t smem_u32(const void* p) {
    uint32_t a;
    asm("{ .reg .u64 t; cvta.to.shared.u64 t, %1; cvt.u32.u64 %0, t; }"
        : "=r"(a) : "l"(p));
    return a;
}

// ---------------------------------------------------------------------------
// Pass 1: transpose+permute [B, C, H*W] -> [B, H*W, C_perm].
// Tile: 128 channels x 32 spatial. Reads and writes fully coalesced
// (writes are STG.128 of the 4-channel quads).
// ---------------------------------------------------------------------------
__global__ __launch_bounds__(256)
void transpose_kernel(const float* __restrict__ in) {
    __shared__ float tile[CGRP][33];
    const int b  = blockIdx.z;
    const int s0 = blockIdx.x * 32;    // spatial tile origin
    const int c0 = blockIdx.y * CGRP;  // channel group origin
    const int tx = threadIdx.x;        // 0..31
    const int ty = threadIdx.y;        // 0..7

    const float* src = in + (size_t)b * CV * SV;
    float* dst = g_feat_t + (size_t)b * SV * CV;

    #pragma unroll
    for (int cc = 0; cc < CGRP; cc += 8)
        tile[cc + ty][tx] = src[(size_t)(c0 + cc + ty) * SV + (s0 + tx)];

    __syncthreads();

    // Write: lane tx emits the quad {tx, tx+32, tx+64, tx+96} for spatial s.
    #pragma unroll
    for (int s = ty; s < 32; s += 8) {
        float4 v;
        v.x = tile[tx      ][s];
        v.y = tile[tx + 32 ][s];
        v.z = tile[tx + 64 ][s];
        v.w = tile[tx + 96 ][s];
        *(float4*)(dst + (size_t)(s0 + s) * CV + c0 + 4 * tx) = v;
    }
}

// ---------------------------------------------------------------------------
// Pass 2: RoIAlign gather + bilerp.
// Block = 256 threads (8 warps) over 128 channels of one roi.
// Warp w handles bins j = w, w+8, ... Each lane gathers float4 (4 channels)
// per corner -> LDG.128, 64B in flight per bin per thread.
// Results staged in true-channel-order [c][49] (conflict-free scalar STS,
// bank = 17*lane + const). The stage IS the contiguous output slab, so the
// writeback is a single 1D TMA bulk store (smem -> global): no LDS/STG
// wavefronts, no register round-trip, no issue slots.
// ---------------------------------------------------------------------------
__global__ __launch_bounds__(256, 6)
void roialign_kernel(const float* __restrict__ rois, float* __restrict__ out) {
    __shared__ float4 sp[NBINS];                         // { base_bits, hr, wr, valid }
    __shared__ alignas(16) float stage[CGRP * NBINS];    // 25088 B == output slab

    const int n    = blockIdx.y;
    const int c0   = blockIdx.x * CGRP;
    const int tid  = threadIdx.x;
    const int w    = tid >> 5;               // warp 0..7
    const int lane = tid & 31;

    if (tid < NBINS) {
        const float* r = rois + (size_t)n * 5;
        const int   bi = (int)r[0];
        const float x1 = r[1] * SPATIAL_SCALE;
        const float y1 = r[2] * SPATIAL_SCALE;
        const float x2 = r[3] * SPATIAL_SCALE;
        const float y2 = r[4] * SPATIAL_SCALE;
        const float bin_w = fmaxf(x2 - x1, 0.0f) / (float)(AWV - 1);
        const float bin_h = fmaxf(y2 - y1, 0.0f) / (float)(AHV - 1);

        const int ph = tid / AWV;
        const int pw = tid % AWV;
        const float h  = y1 + (float)ph * bin_h;
        const float wq = x1 + (float)pw * bin_w;

        const float hstart = fminf(floorf(h),  (float)(HV - 2));
        const float wstart = fminf(floorf(wq), (float)(WV - 2));
        const float hr = h  - hstart;   // may exceed 1 near boundary (matches ref)
        const float wr = wq - wstart;

        const int hs = min(max((int)hstart, 0), HV - 2);
        const int ws = min(max((int)wstart, 0), WV - 2);
        const bool v = (h  >= 0.0f) && (h  < (float)HV) &&
                       (wq >= 0.0f) && (wq < (float)WV);

        const int base = ((bi * HV + hs) * WV + ws) * CV + c0;
        sp[tid] = make_float4(__int_as_float(base), hr, wr, v ? 1.0f : 0.0f);
    }
    __syncthreads();

    const float* __restrict__ f = g_feat_t;

    #pragma unroll 7
    for (int j = w; j < NBINS; j += 8) {
        const float4 p   = sp[j];
        const int    off = __float_as_int(p.x) + 4 * lane;
        const float4 ul = *(const float4*)(f + off);
        const float4 ur = *(const float4*)(f + off + CV);            // w+1
        const float4 dl = *(const float4*)(f + off + WV * CV);       // h+1
        const float4 dr = *(const float4*)(f + off + WV * CV + CV);  // h+1, w+1
        const float hr = p.y, wr = p.z, vv = p.w;

        float t, bo;
        t  = fmaf(wr, ur.x - ul.x, ul.x);
        bo = fmaf(wr, dr.x - dl.x, dl.x);
        stage[(lane      ) * NBINS + j] = fmaf(hr, bo - t, t) * vv;  // chan lane
        t  = fmaf(wr, ur.y - ul.y, ul.y);
        bo = fmaf(wr, dr.y - dl.y, dl.y);
        stage[(lane + 32 ) * NBINS + j] = fmaf(hr, bo - t, t) * vv;  // chan lane+32
        t  = fmaf(wr, ur.z - ul.z, ul.z);
        bo = fmaf(wr, dr.z - dl.z, dl.z);
        stage[(lane + 64 ) * NBINS + j] = fmaf(hr, bo - t, t) * vv;  // chan lane+64
        t  = fmaf(wr, ur.w - ul.w, ul.w);
        bo = fmaf(wr, dr.w - dl.w, dl.w);
        stage[(lane + 96 ) * NBINS + j] = fmaf(hr, bo - t, t) * vv;  // chan lane+96
    }
    __syncthreads();

    // Single 1D bulk async store: stage (25088 B) -> output slab for
    // channels [c0, c0+128) of roi n. Base offset is a multiple of 25088 B
    // (16B-aligned); size is a multiple of 16B.
    if (tid == 0) {
        float* gdst = out + ((size_t)n * CV + c0) * NBINS;
        const uint32_t ssrc = smem_u32(stage);
        asm volatile("fence.proxy.async.shared::cta;" ::: "memory");
        asm volatile(
            "cp.async.bulk.global.shared::cta.bulk_group [%0], [%1], %2;"
            :: "l"(gdst), "r"(ssrc), "n"(CGRP * NBINS * 4)
            : "memory");
        asm volatile("cp.async.bulk.commit_group;" ::: "memory");
        // Wait until TMA has finished READING smem before the CTA can retire
        // (smem may be reallocated to another block otherwise).
        asm volatile("cp.async.bulk.wait_group.read 0;" ::: "memory");
    }
}

// ---------------------------------------------------------------------------
extern "C" void kernel_launch(void* const* d_in, const int* in_sizes, int n_in,
                              void* d_out, int out_size) {
    const float* features = (const float*)d_in[0];
    const float* rois     = (const float*)d_in[1];
    float* out            = (float*)d_out;

    const int N = in_sizes[1] / 5;   // 2048 rois

    dim3 tgrid(SV / 32, CV / CGRP, BV);   // (128, 8, 4)
    transpose_kernel<<<tgrid, dim3(32, 8)>>>(features);

    dim3 grid(CV / CGRP, N);              // (8, 2048)
    roialign_kernel<<<grid, 256>>>(rois, out);
}

// round 9
// speedup vs baseline: 1.1114x; 1.1114x over previous
#include <cuda_runtime.h>
#include <cstdint>

// Problem constants (fixed shapes per reference setup_inputs)
#define BV 4
#define CV 1024
#define HV 64
#define WV 64
#define SV (HV*WV)          // 4096 spatial positions
#define AHV 7
#define AWV 7
#define NBINS (AHV*AWV)     // 49
#define CGRP 128            // channels per block (one permuted group)
#define NROI 2048
#define SPATIAL_SCALE 0.0625f

// Scratch 1: features as [B, H, W, C'] where C' is permuted within each
// 128-channel group: the float4 at lane L holds channels {L, L+32, L+64, L+96}.
// 64 MiB static device allocation (allowed scratch).
__device__ float g_feat_t[(size_t)BV * HV * WV * CV];

// Scratch 2: precomputed per-(roi,bin) params: { base_offset_bits, hr, wr, valid }
// base_offset excludes the channel-group offset (added per block).
__device__ float4 g_params[NROI * NBINS];   // 1.57 MB

// ---------------------------------------------------------------------------
// Pass 0: per-(roi,bin) parameter precompute. 2048*49 = 100352 threads.
// Runs before the transpose; its latency is hidden behind it.
// ---------------------------------------------------------------------------
__global__ __launch_bounds__(256)
void param_kernel(const float* __restrict__ rois) {
    const int idx = blockIdx.x * 256 + threadIdx.x;
    if (idx >= NROI * NBINS) return;
    const int n   = idx / NBINS;
    const int bin = idx % NBINS;

    const float* r = rois + (size_t)n * 5;
    const int   bi = (int)r[0];
    const float x1 = r[1] * SPATIAL_SCALE;
    const float y1 = r[2] * SPATIAL_SCALE;
    const float x2 = r[3] * SPATIAL_SCALE;
    const float y2 = r[4] * SPATIAL_SCALE;
    const float bin_w = fmaxf(x2 - x1, 0.0f) / (float)(AWV - 1);
    const float bin_h = fmaxf(y2 - y1, 0.0f) / (float)(AHV - 1);

    const int ph = bin / AWV;
    const int pw = bin % AWV;
    const float h  = y1 + (float)ph * bin_h;
    const float wq = x1 + (float)pw * bin_w;

    const float hstart = fminf(floorf(h),  (float)(HV - 2));
    const float wstart = fminf(floorf(wq), (float)(WV - 2));
    const float hr = h  - hstart;   // may exceed 1 near boundary (matches ref)
    const float wr = wq - wstart;

    const int hs = min(max((int)hstart, 0), HV - 2);
    const int ws = min(max((int)wstart, 0), WV - 2);
    const bool v = (h  >= 0.0f) && (h  < (float)HV) &&
                   (wq >= 0.0f) && (wq < (float)WV);

    const int base = ((bi * HV + hs) * WV + ws) * CV;
    g_params[idx] = make_float4(__int_as_float(base), hr, wr, v ? 1.0f : 0.0f);
}

// ---------------------------------------------------------------------------
// Pass 1: transpose+permute [B, C, H*W] -> [B, H*W, C_perm].
// Tile: 128 channels x 32 spatial; both directions fully coalesced.
// ---------------------------------------------------------------------------
__global__ __launch_bounds__(256)
void transpose_kernel(const float* __restrict__ in) {
    __shared__ float tile[CGRP][33];
    const int b  = blockIdx.z;
    const int s0 = blockIdx.x * 32;    // spatial tile origin
    const int c0 = blockIdx.y * CGRP;  // channel group origin
    const int tx = threadIdx.x;        // 0..31
    const int ty = threadIdx.y;        // 0..7

    const float* src = in + (size_t)b * CV * SV;
    float* dst = g_feat_t + (size_t)b * SV * CV;

    #pragma unroll
    for (int cc = 0; cc < CGRP; cc += 8)
        tile[cc + ty][tx] = __ldcs(src + (size_t)(c0 + cc + ty) * SV + (s0 + tx));

    __syncthreads();

    #pragma unroll
    for (int s = ty; s < 32; s += 8) {
        float4 v;
        v.x = tile[tx      ][s];
        v.y = tile[tx + 32 ][s];
        v.z = tile[tx + 64 ][s];
        v.w = tile[tx + 96 ][s];
        *(float4*)(dst + (size_t)(s0 + s) * CV + c0 + 4 * tx) = v;
    }
}

// ---------------------------------------------------------------------------
// Pass 2: RoIAlign gather + bilerp.
// Block = 256 threads (8 warps) over 128 channels of one roi. Warp w handles
// bins j = w, w+8, ...; each lane gathers float4 (4 channels) per corner.
// Params come precomputed from g_params (49 LDG.128, L2-hit).
// Results staged in true-channel-order [c][49] (conflict-free scalar STS),
// then streamed out as contiguous float4 slab with evict-first stores.
// ---------------------------------------------------------------------------
__global__ __launch_bounds__(256, 6)
void roialign_kernel(float* __restrict__ out) {
    __shared__ float4 sp[NBINS];                       // packed params
    __shared__ alignas(16) float stage[CGRP * NBINS];  // 25088 B == output slab

    const int n    = blockIdx.y;
    const int c0   = blockIdx.x * CGRP;
    const int tid  = threadIdx.x;
    const int w    = tid >> 5;               // warp 0..7
    const int lane = tid & 31;

    if (tid < NBINS)
        sp[tid] = __ldg(&g_params[n * NBINS + tid]);
    __syncthreads();

    const float* __restrict__ f = g_feat_t;

    #pragma unroll 7
    for (int j = w; j < NBINS; j += 8) {
        const float4 p   = sp[j];
        const int    off = __float_as_int(p.x) + c0 + 4 * lane;
        const float4 ul = *(const float4*)(f + off);
        const float4 ur = *(const float4*)(f + off + CV);            // w+1
        const float4 dl = *(const float4*)(f + off + WV * CV);       // h+1
        const float4 dr = *(const float4*)(f + off + WV * CV + CV);  // h+1, w+1
        const float hr = p.y, wr = p.z, vv = p.w;

        float t, bo;
        t  = fmaf(wr, ur.x - ul.x, ul.x);
        bo = fmaf(wr, dr.x - dl.x, dl.x);
        stage[(lane      ) * NBINS + j] = fmaf(hr, bo - t, t) * vv;  // chan lane
        t  = fmaf(wr, ur.y - ul.y, ul.y);
        bo = fmaf(wr, dr.y - dl.y, dl.y);
        stage[(lane + 32 ) * NBINS + j] = fmaf(hr, bo - t, t) * vv;  // chan lane+32
        t  = fmaf(wr, ur.z - ul.z, ul.z);
        bo = fmaf(wr, dr.z - dl.z, dl.z);
        stage[(lane + 64 ) * NBINS + j] = fmaf(hr, bo - t, t) * vv;  // chan lane+64
        t  = fmaf(wr, ur.w - ul.w, ul.w);
        bo = fmaf(wr, dr.w - dl.w, dl.w);
        stage[(lane + 96 ) * NBINS + j] = fmaf(hr, bo - t, t) * vv;  // chan lane+96
    }
    __syncthreads();

    // Coalesced float4 writeback with evict-first (.cs) streaming stores:
    // keeps the 67 MB feature set resident in L2 under the 411 MB out-stream.
    float4* __restrict__ o4 = (float4*)(out + ((size_t)n * CV + c0) * NBINS);
    const float4* __restrict__ s4 = (const float4*)stage;
    #pragma unroll
    for (int i = tid; i < (CGRP * NBINS) / 4; i += 256)
        __stcs(o4 + i, s4[i]);
}

// ---------------------------------------------------------------------------
extern "C" void kernel_launch(void* const* d_in, const int* in_sizes, int n_in,
                              void* d_out, int out_size) {
    const float* features = (const float*)d_in[0];
    const float* rois     = (const float*)d_in[1];
    float* out            = (float*)d_out;

    param_kernel<<<(NROI * NBINS + 255) / 256, 256>>>(rois);

    dim3 tgrid(SV / 32, CV / CGRP, BV);   // (128, 8, 4)
    transpose_kernel<<<tgrid, dim3(32, 8)>>>(features);

    dim3 grid(CV / CGRP, NROI);           // (8, 2048)
    roialign_kernel<<<grid, 256>>>(out);
}

// round 10
// speedup vs baseline: 1.1453x; 1.0305x over previous
#include <cuda_runtime.h>
#include <cstdint>

// Problem constants (fixed shapes per reference setup_inputs)
#define BV 4
#define CV 1024
#define HV 64
#define WV 64
#define SV (HV*WV)          // 4096 spatial positions
#define AHV 7
#define AWV 7
#define NBINS (AHV*AWV)     // 49
#define CGRP 128            // channels per block (one permuted group)
#define NROI 2048
#define SPATIAL_SCALE 0.0625f

#define TR_BLOCKS (128 * 8 * 4)                 // 4096 transpose role blocks
#define PAR_BLOCKS ((NROI * NBINS + 255) / 256) // 392 param role blocks

// Scratch 1: features as [B, H, W, C'] where C' is permuted within each
// 128-channel group: the float4 at lane L holds channels {L, L+32, L+64, L+96}.
__device__ float g_feat_t[(size_t)BV * HV * WV * CV];

// Scratch 2: precomputed per-(roi,bin) params: { base_offset_bits, hr, wr, valid }
// base_offset excludes the channel-group offset (added per block).
__device__ float4 g_params[NROI * NBINS];   // 1.57 MB

// ---------------------------------------------------------------------------
// Pass 1 (fused): transpose+permute [B,C,H*W] -> [B,H*W,C_perm]  AND
// per-(roi,bin) param precompute, role selected by flat blockIdx.
// ---------------------------------------------------------------------------
__global__ __launch_bounds__(256)
void prep_kernel(const float* __restrict__ in, const float* __restrict__ rois) {
    const int bid = blockIdx.x;
    const int tid = threadIdx.x;

    if (bid < TR_BLOCKS) {
        // ---- transpose role: tile 128 channels x 32 spatial ----
        __shared__ float tile[CGRP][33];
        const int b   = bid >> 10;            // /1024
        const int c0g = (bid >> 7) & 7;       // /128 % 8
        const int s0  = (bid & 127) * 32;
        const int c0  = c0g * CGRP;
        const int tx  = tid & 31;
        const int ty  = tid >> 5;             // 0..7

        const float* src = in + (size_t)b * CV * SV;
        float* dst = g_feat_t + (size_t)b * SV * CV;

        #pragma unroll
        for (int cc = 0; cc < CGRP; cc += 8)
            tile[cc + ty][tx] = __ldcs(src + (size_t)(c0 + cc + ty) * SV + (s0 + tx));

        __syncthreads();

        #pragma unroll
        for (int s = ty; s < 32; s += 8) {
            float4 v;
            v.x = tile[tx      ][s];
            v.y = tile[tx + 32 ][s];
            v.z = tile[tx + 64 ][s];
            v.w = tile[tx + 96 ][s];
            *(float4*)(dst + (size_t)(s0 + s) * CV + c0 + 4 * tx) = v;
        }
    } else {
        // ---- param role ----
        const int idx = (bid - TR_BLOCKS) * 256 + tid;
        if (idx >= NROI * NBINS) return;
        const int n   = idx / NBINS;
        const int bin = idx % NBINS;

        const float* r = rois + (size_t)n * 5;
        const int   bi = (int)r[0];
        const float x1 = r[1] * SPATIAL_SCALE;
        const float y1 = r[2] * SPATIAL_SCALE;
        const float x2 = r[3] * SPATIAL_SCALE;
        const float y2 = r[4] * SPATIAL_SCALE;
        const float bin_w = fmaxf(x2 - x1, 0.0f) / (float)(AWV - 1);
        const float bin_h = fmaxf(y2 - y1, 0.0f) / (float)(AHV - 1);

        const int ph = bin / AWV;
        const int pw = bin % AWV;
        const float h  = y1 + (float)ph * bin_h;
        const float wq = x1 + (float)pw * bin_w;

        const float hstart = fminf(floorf(h),  (float)(HV - 2));
        const float wstart = fminf(floorf(wq), (float)(WV - 2));
        const float hr = h  - hstart;   // may exceed 1 near boundary (matches ref)
        const float wr = wq - wstart;

        const int hs = min(max((int)hstart, 0), HV - 2);
        const int ws = min(max((int)wstart, 0), WV - 2);
        const bool v = (h  >= 0.0f) && (h  < (float)HV) &&
                       (wq >= 0.0f) && (wq < (float)WV);

        const int base = ((bi * HV + hs) * WV + ws) * CV;
        g_params[idx] = make_float4(__int_as_float(base), hr, wr, v ? 1.0f : 0.0f);
    }
}

// ---------------------------------------------------------------------------
// Pass 2: RoIAlign gather + bilerp, software-pipelined.
// Block = 256 threads (8 warps) over 128 channels of one roi. Warp w handles
// bins j = w, w+8, ...; each lane gathers float4 (4 channels) per corner.
// While bin j is computed, bin j+8's params + 4 corners are already in flight.
// ---------------------------------------------------------------------------
__global__ __launch_bounds__(256, 5)
void roialign_kernel(float* __restrict__ out) {
    __shared__ float4 sp[NBINS];                       // packed params
    __shared__ alignas(16) float stage[CGRP * NBINS];  // 25088 B == output slab

    const int n    = blockIdx.y;
    const int c0   = blockIdx.x * CGRP;
    const int tid  = threadIdx.x;
    const int w    = tid >> 5;               // warp 0..7
    const int lane = tid & 31;

    if (tid < NBINS)
        sp[tid] = __ldg(&g_params[n * NBINS + tid]);
    __syncthreads();

    const float* __restrict__ f = g_feat_t;
    const int lc = c0 + 4 * lane;

    // Prologue: load bin j = w
    float4 p = sp[w];
    int off = __float_as_int(p.x) + lc;
    float4 ul = *(const float4*)(f + off);
    float4 ur = *(const float4*)(f + off + CV);
    float4 dl = *(const float4*)(f + off + WV * CV);
    float4 dr = *(const float4*)(f + off + WV * CV + CV);

    #pragma unroll
    for (int j = w; j < NBINS; j += 8) {
        // Prefetch bin j+8 while computing bin j
        float4 pn, uln, urn, dln, drn;
        const int jn = j + 8;
        if (jn < NBINS) {
            pn = sp[jn];
            const int offn = __float_as_int(pn.x) + lc;
            uln = *(const float4*)(f + offn);
            urn = *(const float4*)(f + offn + CV);
            dln = *(const float4*)(f + offn + WV * CV);
            drn = *(const float4*)(f + offn + WV * CV + CV);
        }

        const float hr = p.y, wr = p.z, vv = p.w;
        float t, bo;
        t  = fmaf(wr, ur.x - ul.x, ul.x);
        bo = fmaf(wr, dr.x - dl.x, dl.x);
        stage[(lane      ) * NBINS + j] = fmaf(hr, bo - t, t) * vv;  // chan lane
        t  = fmaf(wr, ur.y - ul.y, ul.y);
        bo = fmaf(wr, dr.y - dl.y, dl.y);
        stage[(lane + 32 ) * NBINS + j] = fmaf(hr, bo - t, t) * vv;  // chan lane+32
        t  = fmaf(wr, ur.z - ul.z, ul.z);
        bo = fmaf(wr, dr.z - dl.z, dl.z);
        stage[(lane + 64 ) * NBINS + j] = fmaf(hr, bo - t, t) * vv;  // chan lane+64
        t  = fmaf(wr, ur.w - ul.w, ul.w);
        bo = fmaf(wr, dr.w - dl.w, dl.w);
        stage[(lane + 96 ) * NBINS + j] = fmaf(hr, bo - t, t) * vv;  // chan lane+96

        p = pn; ul = uln; ur = urn; dl = dln; dr = drn;
    }
    __syncthreads();

    // Coalesced float4 writeback, evict-first (.cs) streaming stores.
    float4* __restrict__ o4 = (float4*)(out + ((size_t)n * CV + c0) * NBINS);
    const float4* __restrict__ s4 = (const float4*)stage;
    #pragma unroll
    for (int i = tid; i < (CGRP * NBINS) / 4; i += 256)
        __stcs(o4 + i, s4[i]);
}

// ---------------------------------------------------------------------------
extern "C" void kernel_launch(void* const* d_in, const int* in_sizes, int n_in,
                              void* d_out, int out_size) {
    const float* features = (const float*)d_in[0];
    const float* rois     = (const float*)d_in[1];
    float* out            = (float*)d_out;

    prep_kernel<<<TR_BLOCKS + PAR_BLOCKS, 256>>>(features, rois);

    dim3 grid(CV / CGRP, NROI);           // (8, 2048)
    roialign_kernel<<<grid, 256>>>(out);
}